// round 16
// baseline (speedup 1.0000x reference)
#include <cuda_runtime.h>
#include <cuda_fp16.h>
#include <math.h>

#define NV 5
#define HIMG 512
#define WIMG 640
#define CFE 32
#define ND 128
#define HFE 64
#define WFE 80
#define H1 256
#define W1 320
#define H2 128
#define W2 160
#define HWF (HFE*WFE)
#define HWI (HIMG*WIMG)

// padded cost volume dims (1-cell halo in d, y, x)
#define DP 130
#define YP 66
#define XP 82
#define NPADPIX (DP*YP*XP)

// ---------------- scratch (device globals, no allocation) ----------------
__device__ float g_e1[NV*8*H1*W1];
__device__ float g_e2[NV*16*H2*W2];
__device__ uint2 g_featsh2[NV*8*HWF];         // fp16 plane-major: [v][c4][y*x] 4 halves
__device__ uint4 g_costp4[NPADPIX*4];         // fp16 pixel-major padded [dp][yp][xp][32ic]
__device__ uint4 g_reg1h4[ND*HWF];            // fp16 pixel-major: [d,y,x][8 oc halves]
__device__ float g_cost2[ND*HWF];             // (d,y,x)
__device__ float g_conf[HWF];
__device__ float g_regd[HWF];
__device__ float g_regup[HWI];
__device__ uint4 g_hiddenh4[HWI*4];           // fp16 pixel-major: [y*x][32 ch halves]
__device__ float g_Hm[4*9];
__device__ float g_bb[4*3];
__device__ float g_depths[ND];

// ---------------- setup: depths + homographies ----------------
__global__ void setup_kernel(const float* __restrict__ K, const float* __restrict__ poses) {
    for (int i = 0; i < ND; i++) {
        float inv = 2.0f + (float)i * (0.2f - 2.0f) / 127.0f;
        g_depths[i] = 1.0f / inv;
    }
    float fx = K[0] / 8.0f, cx = K[2] / 8.0f, fy = K[4] / 8.0f, cy = K[5] / 8.0f;
    float Kf[9] = {fx, 0, cx, 0, fy, cy, 0, 0, 1};
    float Ki[9] = {1.0f/fx, 0, -cx/fx, 0, 1.0f/fy, -cy/fy, 0, 0, 1};
    float R0T[9], ti[3];
    for (int r = 0; r < 3; r++)
        for (int c = 0; c < 3; c++) R0T[r*3+c] = poses[c*4+r];
    for (int r = 0; r < 3; r++) {
        float s = 0;
        for (int c = 0; c < 3; c++) s += R0T[r*3+c] * poses[c*4+3];
        ti[r] = -s;
    }
    for (int v = 1; v < NV; v++) {
        const float* P = poses + v*16;
        float Rt[9], tt[3], A[9];
        for (int r = 0; r < 3; r++)
            for (int c = 0; c < 3; c++) {
                float s = 0;
                for (int k = 0; k < 3; k++) s += P[r*4+k] * R0T[k*3+c];
                Rt[r*3+c] = s;
            }
        for (int r = 0; r < 3; r++) {
            float s = 0;
            for (int k = 0; k < 3; k++) s += P[r*4+k] * ti[k];
            tt[r] = s + P[r*4+3];
        }
        for (int r = 0; r < 3; r++)
            for (int c = 0; c < 3; c++) {
                float s = 0;
                for (int k = 0; k < 3; k++) s += Kf[r*3+k] * Rt[k*3+c];
                A[r*3+c] = s;
            }
        for (int r = 0; r < 3; r++)
            for (int c = 0; c < 3; c++) {
                float s = 0;
                for (int k = 0; k < 3; k++) s += A[r*3+k] * Ki[k*3+c];
                g_Hm[(v-1)*9 + r*3 + c] = s;
            }
        for (int r = 0; r < 3; r++) {
            float s = 0;
            for (int k = 0; k < 3; k++) s += Kf[r*3+k] * tt[k];
            g_bb[(v-1)*3 + r] = s;
        }
    }
}

// ---------------- encoder ----------------
// enc1: 3 -> 8 ch, stride 2; thread = (im, y, 2 x-outputs)
__global__ __launch_bounds__(256) void enc1_kernel(const float* __restrict__ img,
                                                   const float* __restrict__ w,
                                                   const float* __restrict__ b) {
    __shared__ float sw[8*3*9];
    __shared__ float sb[8];
    for (int i = threadIdx.x; i < 8*3*9; i += blockDim.x) sw[i] = w[i];
    if (threadIdx.x < 8) sb[threadIdx.x] = b[threadIdx.x];
    __syncthreads();
    int idx = blockIdx.x * blockDim.x + threadIdx.x;
    const int XG = W1/2;  // 160
    if (idx >= NV*H1*XG) return;
    int xg = idx % XG, y = (idx / XG) % H1, im = idx / (XG*H1);
    int xb = xg * 2;
    float acc[8][2];
#pragma unroll
    for (int o = 0; o < 8; o++) {
        float bv = sb[o];
        acc[o][0] = bv; acc[o][1] = bv;
    }
    const float* ib = img + im*3*HWI;
    for (int ic = 0; ic < 3; ic++) {
#pragma unroll
        for (int ky = 0; ky < 3; ky++) {
            int iy = 2*y + ky; if (iy >= HIMG) continue;
            const float* row = ib + (ic*HIMG + iy)*WIMG + 2*xb;
            float v[5];
            float4 q0 = *(const float4*)row;
            v[0]=q0.x; v[1]=q0.y; v[2]=q0.z; v[3]=q0.w;
            v[4] = (2*xb + 4 < WIMG) ? row[4] : 0.0f;
#pragma unroll
            for (int kx = 0; kx < 3; kx++) {
#pragma unroll
                for (int o = 0; o < 8; o++) {
                    float wv = sw[((o*3+ic)*3+ky)*3+kx];
                    acc[o][0] += v[kx] * wv;
                    acc[o][1] += v[2 + kx] * wv;
                }
            }
        }
    }
#pragma unroll
    for (int o = 0; o < 8; o++) {
        g_e1[((im*8+o)*H1 + y)*W1 + xb]     = fmaxf(acc[o][0], 0.0f);
        g_e1[((im*8+o)*H1 + y)*W1 + xb + 1] = fmaxf(acc[o][1], 0.0f);
    }
}

// enc2: 8 -> 16 ch, stride 2; thread = (im, y, 2 x-outputs), oc group of 8 via grid.y
__global__ __launch_bounds__(256) void enc2_kernel(const float* __restrict__ w,
                                                   const float* __restrict__ b) {
    __shared__ float sw[8*8*9];
    __shared__ float sb[8];
    int ocg = blockIdx.y;   // 0..1
    for (int i = threadIdx.x; i < 8*8*9; i += blockDim.x) {
        int o = i / 72, rest = i % 72;
        sw[i] = w[(ocg*8 + o)*72 + rest];
    }
    if (threadIdx.x < 8) sb[threadIdx.x] = b[ocg*8 + threadIdx.x];
    __syncthreads();
    int idx = blockIdx.x * blockDim.x + threadIdx.x;
    const int XG = W2/2;  // 80
    if (idx >= NV*H2*XG) return;
    int xg = idx % XG, y = (idx / XG) % H2, im = idx / (XG*H2);
    int xb = xg * 2;
    float acc[8][2];
#pragma unroll
    for (int o = 0; o < 8; o++) {
        float bv = sb[o];
        acc[o][0] = bv; acc[o][1] = bv;
    }
    const float* ib = g_e1 + im*8*H1*W1;
    for (int ic = 0; ic < 8; ic++) {
#pragma unroll
        for (int ky = 0; ky < 3; ky++) {
            int iy = 2*y + ky; if (iy >= H1) continue;
            const float* row = ib + (ic*H1 + iy)*W1 + 2*xb;
            float v[5];
            float4 q0 = *(const float4*)row;
            v[0]=q0.x; v[1]=q0.y; v[2]=q0.z; v[3]=q0.w;
            v[4] = (2*xb + 4 < W1) ? row[4] : 0.0f;
#pragma unroll
            for (int kx = 0; kx < 3; kx++) {
#pragma unroll
                for (int o = 0; o < 8; o++) {
                    float wv = sw[((o*8+ic)*3+ky)*3+kx];
                    acc[o][0] += v[kx] * wv;
                    acc[o][1] += v[2 + kx] * wv;
                }
            }
        }
    }
#pragma unroll
    for (int o = 0; o < 8; o++) {
        g_e2[((im*16+ocg*8+o)*H2 + y)*W2 + xb]     = fmaxf(acc[o][0], 0.0f);
        g_e2[((im*16+ocg*8+o)*H2 + y)*W2 + xb + 1] = fmaxf(acc[o][1], 0.0f);
    }
}

// enc3: 16 -> 32 ch, stride 2; thread = (im, y, 1 x-output), oc group of 8 via grid.y
__global__ __launch_bounds__(128) void enc3_kernel(const float* __restrict__ w,
                                                   const float* __restrict__ b) {
    __shared__ float sw[8*16*9];
    __shared__ float sb[8];
    int ocg = blockIdx.y;  // 0..3
    for (int i = threadIdx.x; i < 8*16*9; i += blockDim.x) {
        int o = i / 144, rest = i % 144;
        sw[i] = w[(ocg*8 + o)*144 + rest];
    }
    if (threadIdx.x < 8) sb[threadIdx.x] = b[ocg*8 + threadIdx.x];
    __syncthreads();
    int idx = blockIdx.x * blockDim.x + threadIdx.x;
    if (idx >= NV*HFE*WFE) return;
    int x = idx % WFE, y = (idx / WFE) % HFE, im = idx / HWF;
    float acc[8];
#pragma unroll
    for (int o = 0; o < 8; o++) acc[o] = sb[o];
    const float* ib = g_e2 + im*16*H2*W2;
    for (int ic = 0; ic < 16; ic++) {
#pragma unroll
        for (int ky = 0; ky < 3; ky++) {
            int iy = 2*y + ky; if (iy >= H2) continue;
            const float* row = ib + (ic*H2 + iy)*W2 + 2*x;
            float v[3];
            float2 q0 = *(const float2*)row;
            v[0] = q0.x; v[1] = q0.y;
            v[2] = (2*x + 2 < W2) ? row[2] : 0.0f;
#pragma unroll
            for (int kx = 0; kx < 3; kx++) {
#pragma unroll
                for (int o = 0; o < 8; o++)
                    acc[o] += v[kx] * sw[(o*16+ic)*9 + ky*3 + kx];
            }
        }
    }
    int pix = y*WFE + x;
    __half2 l01 = __floats2half2_rn(acc[0], acc[1]);
    __half2 l23 = __floats2half2_rn(acc[2], acc[3]);
    __half2 h01 = __floats2half2_rn(acc[4], acc[5]);
    __half2 h23 = __floats2half2_rn(acc[6], acc[7]);
    uint2 ulo = make_uint2(*reinterpret_cast<unsigned*>(&l01),
                           *reinterpret_cast<unsigned*>(&l23));
    uint2 uhi = make_uint2(*reinterpret_cast<unsigned*>(&h01),
                           *reinterpret_cast<unsigned*>(&h23));
    g_featsh2[(im*8 + ocg*2 + 0)*HWF + pix] = ulo;
    g_featsh2[(im*8 + ocg*2 + 1)*HWF + pix] = uhi;
}

// ---------------- cost volume: fp16 feats in, fp16 padded pixel-major out ----------------
__device__ __forceinline__ void unpack_h4(uint2 u, float& a, float& b, float& c, float& d) {
    __half2 h0 = *reinterpret_cast<__half2*>(&u.x);
    __half2 h1 = *reinterpret_cast<__half2*>(&u.y);
    float2 f0 = __half22float2(h0), f1 = __half22float2(h1);
    a = f0.x; b = f0.y; c = f1.x; d = f1.y;
}

__global__ __launch_bounds__(256) void cost_kernel() {
    int idx = blockIdx.x * blockDim.x + threadIdx.x;
    if (idx >= NPADPIX) return;
    int xp = idx % XP, yp = (idx / XP) % YP, dp = idx / (XP*YP);
    uint2* cp = (uint2*)g_costp4;
    bool interior = (xp >= 1) && (xp <= WFE) && (yp >= 1) && (yp <= HFE)
                 && (dp >= 1) && (dp <= ND);
    if (!interior) {
#pragma unroll
        for (int j = 0; j < 8; j++) cp[idx*8 + j] = make_uint2(0u, 0u);
        return;
    }
    int x = xp - 1, y = yp - 1, d = dp - 1;
    float depth = g_depths[d];
    float xf = (float)x, yf = (float)y;
    float wgt[4][4];
    int   off[4][4];
#pragma unroll
    for (int v = 0; v < 4; v++) {
        const float* Hm = g_Hm + v*9;
        const float* bb = g_bb + v*3;
        float u  = depth*(Hm[0]*xf + Hm[1]*yf + Hm[2]) + bb[0];
        float vv = depth*(Hm[3]*xf + Hm[4]*yf + Hm[5]) + bb[1];
        float z  = depth*(Hm[6]*xf + Hm[7]*yf + Hm[8]) + bb[2];
        float valid = z > 0.001f ? 1.0f : 0.0f;
        float zc = fmaxf(z, 0.001f);
        float px = u / zc, py = vv / zc;
        float fx0 = floorf(px), fy0 = floorf(py);
        float wx = px - fx0, wy = py - fy0;
        int x0 = (int)fx0, y0 = (int)fy0;
        float w00 = (1.0f-wx)*(1.0f-wy)*valid;
        float w01 = wx*(1.0f-wy)*valid;
        float w10 = (1.0f-wx)*wy*valid;
        float w11 = wx*wy*valid;
        bool ix0 = (x0 >= 0) && (x0 < WFE);
        bool ix1 = (x0+1 >= 0) && (x0+1 < WFE);
        bool iy0 = (y0 >= 0) && (y0 < HFE);
        bool iy1 = (y0+1 >= 0) && (y0+1 < HFE);
        if (!(ix0 && iy0)) w00 = 0.0f;
        if (!(ix1 && iy0)) w01 = 0.0f;
        if (!(ix0 && iy1)) w10 = 0.0f;
        if (!(ix1 && iy1)) w11 = 0.0f;
        int cx0 = min(max(x0, 0), WFE-1), cx1 = min(max(x0+1, 0), WFE-1);
        int cy0 = min(max(y0, 0), HFE-1), cy1 = min(max(y0+1, 0), HFE-1);
        wgt[v][0] = w00; wgt[v][1] = w01; wgt[v][2] = w10; wgt[v][3] = w11;
        off[v][0] = cy0*WFE + cx0; off[v][1] = cy0*WFE + cx1;
        off[v][2] = cy1*WFE + cx0; off[v][3] = cy1*WFE + cx1;
    }
    int pix = y*WFE + x;
#pragma unroll 2
    for (int c4 = 0; c4 < 8; c4++) {
        float s0, s1, s2, s3;
        unpack_h4(g_featsh2[c4*HWF + pix], s0, s1, s2, s3);
        float q0 = s0*s0, q1 = s1*s1, q2 = s2*s2, q3 = s3*s3;
#pragma unroll
        for (int v = 0; v < 4; v++) {
            const uint2* pl = g_featsh2 + ((v+1)*8 + c4)*HWF;
            float ax, ay, az, aw, bx, by, bz, bw;
            float cx, cy, cz, cw, ex, ey, ez, ew;
            unpack_h4(pl[off[v][0]], ax, ay, az, aw);
            unpack_h4(pl[off[v][1]], bx, by, bz, bw);
            unpack_h4(pl[off[v][2]], cx, cy, cz, cw);
            unpack_h4(pl[off[v][3]], ex, ey, ez, ew);
            float w00 = wgt[v][0], w01 = wgt[v][1], w10 = wgt[v][2], w11 = wgt[v][3];
            float v0 = w00*ax + w01*bx + w10*cx + w11*ex;
            float v1 = w00*ay + w01*by + w10*cy + w11*ey;
            float v2 = w00*az + w01*bz + w10*cz + w11*ez;
            float v3 = w00*aw + w01*bw + w10*cw + w11*ew;
            s0 += v0; q0 += v0*v0;
            s1 += v1; q1 += v1*v1;
            s2 += v2; q2 += v2*v2;
            s3 += v3; q3 += v3*v3;
        }
        float m0 = s0*0.2f, m1 = s1*0.2f, m2 = s2*0.2f, m3 = s3*0.2f;
        __half2 ha = __floats2half2_rn(q0*0.2f - m0*m0, q1*0.2f - m1*m1);
        __half2 hb = __floats2half2_rn(q2*0.2f - m2*m2, q3*0.2f - m3*m3);
        unsigned ua = *reinterpret_cast<unsigned*>(&ha);
        unsigned ub = *reinterpret_cast<unsigned*>(&hb);
        cp[idx*8 + c4] = make_uint2(ua, ub);
    }
}

// ---------------- reg1: fp16 tensor-core implicit GEMM (27-tap accumulation) ----------------
// block = (1 d x 2 y x 80 x) outputs = 10 warps; warp = m16 (x) x n8 (oc), K = 27 taps x 32 ic
#define R1M_ICS 40                       // smem ic stride (halves) - LDSM conflict-free
#define R1M_A_BYTES (12*82*R1M_ICS*2)    // 3dd x 4yy x 82px x 40 halves = 78720 B
#define R1M_B_BYTES (54*8*16*2)          // 13824 B
#define R1M_SMEM (R1M_A_BYTES + R1M_B_BYTES)

__global__ __launch_bounds__(320) void reg1_mma_kernel(const float* __restrict__ w,
                                                       const float* __restrict__ b) {
    extern __shared__ char sm[];
    __half* sB = (__half*)(sm + R1M_A_BYTES);
    int tid = threadIdx.x;
    int by = blockIdx.x & 31, d0 = blockIdx.x >> 5;
    int y0 = by * 2;

    uint4* sA4 = (uint4*)sm;
    for (int e = tid; e < 12*82*4; e += 320) {
        int u = e & 3;
        int px = (e >> 2) % 82;
        int r = e / 328;
        int kdl = r >> 2, kyl = r & 3;
        int pixpad = (((d0 + kdl)*YP) + (y0 + kyl))*XP + px;
        sA4[(r*82 + px)*5 + u] = g_costp4[pixpad*4 + u];
    }
    for (int e = tid; e < 54*8*16; e += 320) {
        int k = e & 15, oc = (e >> 4) & 7, tc = e >> 7;
        int tap = tc >> 1, ch = tc & 1;
        sB[e] = __float2half(w[oc*864 + (ch*16 + k)*27 + tap]);
    }
    __syncthreads();

    int warp = tid >> 5, lane = tid & 31;
    int ybase = warp / 5, xt = warp % 5;
    int ocp = lane & 3;
    float c0 = b[2*ocp], c1 = b[2*ocp + 1];
    float c2 = c0, c3 = c1;
    unsigned sA_base = (unsigned)__cvta_generic_to_shared(sm);
    unsigned sB_base = (unsigned)__cvta_generic_to_shared(sB);
    int r_l = (lane < 16) ? lane : lane - 16;
    unsigned c_l = (lane < 16) ? 0u : 16u;
    unsigned boff = (unsigned)((lane >> 2)*32 + ocp*4);

#pragma unroll
    for (int kd = 0; kd < 3; kd++) {
#pragma unroll
        for (int ky = 0; ky < 3; ky++) {
#pragma unroll
            for (int kx = 0; kx < 3; kx++) {
                int tap = (kd*3 + ky)*3 + kx;
                int pixrow = (kd*4 + ybase + ky)*82 + xt*16 + kx;
                unsigned abase = sA_base + (unsigned)((pixrow + r_l)*80) + c_l;
#pragma unroll
                for (int ch = 0; ch < 2; ch++) {
                    unsigned aaddr = abase + (unsigned)(ch*32);
                    unsigned a0, a1, a2, a3;
                    asm volatile(
                        "ldmatrix.sync.aligned.m8n8.x4.shared.b16 {%0,%1,%2,%3}, [%4];"
                        : "=r"(a0), "=r"(a1), "=r"(a2), "=r"(a3) : "r"(aaddr));
                    unsigned baddr = sB_base + (unsigned)((tap*2 + ch)*256) + boff;
                    unsigned b0, b1;
                    asm volatile("ld.shared.b32 %0, [%1];" : "=r"(b0) : "r"(baddr));
                    asm volatile("ld.shared.b32 %0, [%1];" : "=r"(b1) : "r"(baddr + 16));
                    asm volatile(
                        "mma.sync.aligned.m16n8k16.row.col.f32.f16.f16.f32 "
                        "{%0,%1,%2,%3}, {%4,%5,%6,%7}, {%8,%9}, {%0,%1,%2,%3};"
                        : "+f"(c0), "+f"(c1), "+f"(c2), "+f"(c3)
                        : "r"(a0), "r"(a1), "r"(a2), "r"(a3), "r"(b0), "r"(b1));
                }
            }
        }
    }

    int y = y0 + ybase;
    __half2* grh = (__half2*)g_reg1h4;
    int row0 = xt*16 + (lane >> 2);
    int base0 = ((d0*HFE + y)*WFE + row0)*4 + ocp;
    int base1 = ((d0*HFE + y)*WFE + row0 + 8)*4 + ocp;
    grh[base0] = __floats2half2_rn(fmaxf(c0, 0.0f), fmaxf(c1, 0.0f));
    grh[base1] = __floats2half2_rn(fmaxf(c2, 0.0f), fmaxf(c3, 0.0f));
}

// reg2: 8 -> 1 ch, 3x3x3 SAME; thread = (d, y, 2 x); taps read as 1x uint4 (8 fp16)
__global__ __launch_bounds__(256) void reg2_kernel(const float* __restrict__ w,
                                                   const float* __restrict__ b) {
    __shared__ float sw[27*8];
    __shared__ float sb0;
    for (int i = threadIdx.x; i < 27*8; i += blockDim.x) {
        int k = i >> 3, oc = i & 7;
        sw[i] = w[oc*27 + k];
    }
    if (threadIdx.x == 0) sb0 = b[0];
    __syncthreads();
    int idx = blockIdx.x * blockDim.x + threadIdx.x;
    const int XG = WFE/2;
    if (idx >= ND*HFE*XG) return;
    int xg = idx % XG, y = (idx / XG) % HFE, d = idx / (XG*HFE);
    int xb = xg * 2;
    float acc0 = sb0, acc1 = sb0;
#pragma unroll
    for (int kd = 0; kd < 3; kd++) {
        int dd = d + kd - 1; if (dd < 0 || dd >= ND) continue;
#pragma unroll
        for (int ky = 0; ky < 3; ky++) {
            int yy = y + ky - 1; if (yy < 0 || yy >= HFE) continue;
            int rowbase = (dd*HFE + yy)*WFE;
            uint4 v[4];
#pragma unroll
            for (int j = 0; j < 4; j++) {
                int xx = xb - 1 + j;
                v[j] = (xx >= 0 && xx < WFE) ? g_reg1h4[rowbase + xx]
                                             : make_uint4(0u, 0u, 0u, 0u);
            }
#pragma unroll
            for (int kx = 0; kx < 3; kx++) {
                const float* wk = sw + (kd*9 + ky*3 + kx)*8;
                const __half2* h0 = (const __half2*)&v[kx];
                const __half2* h1 = (const __half2*)&v[kx+1];
#pragma unroll
                for (int q = 0; q < 4; q++) {
                    float2 f0 = __half22float2(h0[q]);
                    float2 f1 = __half22float2(h1[q]);
                    acc0 += f0.x*wk[2*q] + f0.y*wk[2*q+1];
                    acc1 += f1.x*wk[2*q] + f1.y*wk[2*q+1];
                }
            }
        }
    }
    g_cost2[(d*HFE + y)*WFE + xb]     = acc0;
    g_cost2[(d*HFE + y)*WFE + xb + 1] = acc1;
}

// ---------------- streaming softmax + sum4 confidence + depth regression ----------------
__global__ __launch_bounds__(256) void softmax_kernel() {
    int pix = blockIdx.x * blockDim.x + threadIdx.x;
    if (pix >= HWF) return;
    const float* col = g_cost2 + pix;
    float m = -1e30f;
#pragma unroll 8
    for (int d = 0; d < ND; d++)
        m = fmaxf(m, col[d*HWF]);
    float s = 0.0f, sd = 0.0f, mw = 0.0f;
    float e1 = 0.0f, e2 = 0.0f, e3 = 0.0f;
#pragma unroll 4
    for (int d = 0; d < ND; d++) {
        float e0 = expf(col[d*HWF] - m);
        s += e0;
        sd += e0 * g_depths[d];
        float win = e0 + e1 + e2 + e3;
        if (d >= 3) mw = fmaxf(mw, win);
        e3 = e2; e2 = e1; e1 = e0;
    }
    g_conf[pix] = mw / s;
    g_regd[pix] = sd / s;
}

// ---------------- x8 bilinear upsample ----------------
__global__ __launch_bounds__(256) void upsample_kernel(float* __restrict__ out_conf) {
    int idx = blockIdx.x * blockDim.x + threadIdx.x;
    if (idx >= HWI) return;
    int ox = idx % WIMG, oy = idx / WIMG;
    float fy = (oy + 0.5f) * ((float)HFE / HIMG) - 0.5f;
    float fx = (ox + 0.5f) * ((float)WFE / WIMG) - 0.5f;
    float y0f = floorf(fy), x0f = floorf(fx);
    float wy = fy - y0f, wx = fx - x0f;
    int y0 = (int)y0f, x0 = (int)x0f;
    int y0c = min(max(y0, 0), HFE-1), y1c = min(max(y0+1, 0), HFE-1);
    int x0c = min(max(x0, 0), WFE-1), x1c = min(max(x0+1, 0), WFE-1);
    float w00 = (1.0f-wx)*(1.0f-wy), w01 = wx*(1.0f-wy);
    float w10 = (1.0f-wx)*wy, w11 = wx*wy;
    float cv = w00*g_conf[y0c*WFE+x0c] + w01*g_conf[y0c*WFE+x1c]
             + w10*g_conf[y1c*WFE+x0c] + w11*g_conf[y1c*WFE+x1c];
    float rv = w00*g_regd[y0c*WFE+x0c] + w01*g_regd[y0c*WFE+x1c]
             + w10*g_regd[y1c*WFE+x0c] + w11*g_regd[y1c*WFE+x1c];
    out_conf[idx] = cv;
    g_regup[idx] = rv;
}

// ---------------- refinement ----------------
// refine1: 4 -> 32 ch; stores fp16 pixel-major (4x uint4 per pixel)
__global__ __launch_bounds__(256) void refine1_kernel(const float* __restrict__ img,
                                                      const float* __restrict__ w,
                                                      const float* __restrict__ b) {
    __shared__ float sw[32*4*9];
    __shared__ float sb[32];
    for (int i = threadIdx.x; i < 32*4*9; i += blockDim.x) sw[i] = w[i];
    if (threadIdx.x < 32) sb[threadIdx.x] = b[threadIdx.x];
    __syncthreads();
    int id = blockIdx.x * blockDim.x + threadIdx.x;
    const int XG = WIMG/4;
    if (id >= HIMG*XG) return;
    int ocg = blockIdx.y;
    int xg = id % XG, y = id / XG;
    int xb = xg * 4;
    float acc[16][4];
#pragma unroll
    for (int o = 0; o < 16; o++) {
        float bv = sb[ocg*16 + o];
#pragma unroll
        for (int xi = 0; xi < 4; xi++) acc[o][xi] = bv;
    }
    for (int ic = 0; ic < 4; ic++) {
        const float* src = (ic < 3) ? (img + ic*HWI) : g_regup;
#pragma unroll
        for (int ky = 0; ky < 3; ky++) {
            int yy = y + ky - 1; if (yy < 0 || yy >= HIMG) continue;
            const float* row = src + yy*WIMG;
            float vals[6];
#pragma unroll
            for (int j = 0; j < 6; j++) {
                int xx = xb - 1 + j;
                vals[j] = (xx >= 0 && xx < WIMG) ? row[xx] : 0.0f;
            }
#pragma unroll
            for (int kx = 0; kx < 3; kx++) {
#pragma unroll
                for (int o = 0; o < 16; o++) {
                    float wv = sw[(((ocg*16 + o)*4 + ic)*3 + ky)*3 + kx];
#pragma unroll
                    for (int xi = 0; xi < 4; xi++)
                        acc[o][xi] += vals[kx + xi] * wv;
                }
            }
        }
    }
#pragma unroll
    for (int xi = 0; xi < 4; xi++) {
        int pix = y*WIMG + xb + xi;
#pragma unroll
        for (int q2 = 0; q2 < 2; q2++) {
            __half2 hs[4];
#pragma unroll
            for (int p = 0; p < 4; p++)
                hs[p] = __floats2half2_rn(fmaxf(acc[q2*8 + 2*p][xi], 0.0f),
                                          fmaxf(acc[q2*8 + 2*p + 1][xi], 0.0f));
            uint4 u;
            u.x = *reinterpret_cast<unsigned*>(&hs[0]);
            u.y = *reinterpret_cast<unsigned*>(&hs[1]);
            u.z = *reinterpret_cast<unsigned*>(&hs[2]);
            u.w = *reinterpret_cast<unsigned*>(&hs[3]);
            g_hiddenh4[pix*4 + ocg*2 + q2] = u;
        }
    }
}

// refine2: 32 -> 1 ch; taps read as 4x uint4 (32 fp16)
__global__ __launch_bounds__(256) void refine2_kernel(const float* __restrict__ w,
                                                      const float* __restrict__ b,
                                                      float* __restrict__ out_ref) {
    __shared__ float sw[32*9];
    __shared__ float sb0;
    for (int i = threadIdx.x; i < 32*9; i += blockDim.x) sw[i] = w[i];
    if (threadIdx.x == 0) sb0 = b[0];
    __syncthreads();
    int idx = blockIdx.x * blockDim.x + threadIdx.x;
    if (idx >= HWI) return;
    int x = idx % WIMG, y = idx / WIMG;
    float acc = sb0;
#pragma unroll
    for (int ky = 0; ky < 3; ky++) {
        int yy = y + ky - 1; if (yy < 0 || yy >= HIMG) continue;
#pragma unroll
        for (int kx = 0; kx < 3; kx++) {
            int xx = x + kx - 1; if (xx < 0 || xx >= WIMG) continue;
            int pix = yy*WIMG + xx;
            int tap = ky*3 + kx;
#pragma unroll
            for (int q = 0; q < 4; q++) {
                uint4 h4 = g_hiddenh4[pix*4 + q];
                const __half2* hp = (const __half2*)&h4;
#pragma unroll
                for (int p = 0; p < 4; p++) {
                    float2 f = __half22float2(hp[p]);
                    acc += f.x * sw[(q*8 + 2*p)*9 + tap];
                    acc += f.y * sw[(q*8 + 2*p + 1)*9 + tap];
                }
            }
        }
    }
    out_ref[idx] = g_regup[idx] + acc;
}

// ---------------- launch ----------------
extern "C" void kernel_launch(void* const* d_in, const int* in_sizes, int n_in,
                              void* d_out, int out_size) {
    const float* images = (const float*)d_in[0];
    const float* K      = (const float*)d_in[1];
    const float* poses  = (const float*)d_in[2];
    const float* enc_w1 = (const float*)d_in[3];
    const float* enc_b1 = (const float*)d_in[4];
    const float* enc_w2 = (const float*)d_in[5];
    const float* enc_b2 = (const float*)d_in[6];
    const float* enc_w3 = (const float*)d_in[7];
    const float* enc_b3 = (const float*)d_in[8];
    const float* reg_w1 = (const float*)d_in[9];
    const float* reg_b1 = (const float*)d_in[10];
    const float* reg_w2 = (const float*)d_in[11];
    const float* reg_b2 = (const float*)d_in[12];
    const float* ref_w1 = (const float*)d_in[13];
    const float* ref_b1 = (const float*)d_in[14];
    const float* ref_w2 = (const float*)d_in[15];
    const float* ref_b2 = (const float*)d_in[16];
    float* out = (float*)d_out;

    cudaFuncSetAttribute(reg1_mma_kernel, cudaFuncAttributeMaxDynamicSharedMemorySize,
                         R1M_SMEM);

    setup_kernel<<<1, 1>>>(K, poses);
    enc1_kernel<<<(NV*H1*(W1/2) + 255)/256, 256>>>(images, enc_w1, enc_b1);
    dim3 g2((NV*H2*(W2/2) + 255)/256, 2);
    enc2_kernel<<<g2, 256>>>(enc_w2, enc_b2);
    dim3 g3((NV*HFE*WFE + 127)/128, 4);
    enc3_kernel<<<g3, 128>>>(enc_w3, enc_b3);
    cost_kernel<<<(NPADPIX + 255)/256, 256>>>();
    reg1_mma_kernel<<<ND*32, 320, R1M_SMEM>>>(reg_w1, reg_b1);
    reg2_kernel<<<(ND*HFE*(WFE/2) + 255)/256, 256>>>(reg_w2, reg_b2);
    softmax_kernel<<<(HWF + 255)/256, 256>>>();
    upsample_kernel<<<(HWI + 255)/256, 256>>>(out);
    dim3 g1((HIMG*(WIMG/4) + 255)/256, 2);
    refine1_kernel<<<g1, 256>>>(images, ref_w1, ref_b1);
    refine2_kernel<<<(HWI + 255)/256, 256>>>(ref_w2, ref_b2, out + HWI);
}

// round 17
// speedup vs baseline: 1.0405x; 1.0405x over previous
#include <cuda_runtime.h>
#include <cuda_fp16.h>
#include <math.h>

#define NV 5
#define HIMG 512
#define WIMG 640
#define CFE 32
#define ND 128
#define HFE 64
#define WFE 80
#define H1 256
#define W1 320
#define H2 128
#define W2 160
#define HWF (HFE*WFE)
#define HWI (HIMG*WIMG)

// padded cost volume dims (1-cell halo in d, y, x)
#define DP 130
#define YP 66
#define XP 82
#define NPADPIX (DP*YP*XP)

// ---------------- scratch (device globals, no allocation) ----------------
__device__ float g_e1[NV*8*H1*W1];
__device__ float g_e2[NV*16*H2*W2];
__device__ uint2 g_featsh2[NV*8*HWF];         // fp16 plane-major: [v][c4][y*x] 4 halves
__device__ uint4 g_costp4[NPADPIX*4];         // fp16 pixel-major padded [dp][yp][xp][32ic]
__device__ uint4 g_reg1h4[ND*HWF];            // fp16 pixel-major: [d,y,x][8 oc halves]
__device__ float g_cost2[ND*HWF];             // (d,y,x)
__device__ float g_conf[HWF];
__device__ float g_regd[HWF];
__device__ float g_regup[HWI];
__device__ uint4 g_hiddenh4[HWI*4];           // fp16 pixel-major: [y*x][32 ch halves]
__device__ float g_Hm[4*9];
__device__ float g_bb[4*3];
__device__ float g_depths[ND];

// ---------------- f32x2 helpers ----------------
__device__ __forceinline__ unsigned long long pk2(float lo, float hi) {
    unsigned long long r;
    asm("mov.b64 %0, {%1, %2};" : "=l"(r) : "f"(lo), "f"(hi));
    return r;
}
__device__ __forceinline__ void upk2(float& lo, float& hi, unsigned long long v) {
    asm("mov.b64 {%0, %1}, %2;" : "=f"(lo), "=f"(hi) : "l"(v));
}
__device__ __forceinline__ unsigned long long fma2(unsigned long long a,
                                                   unsigned long long b,
                                                   unsigned long long c) {
    unsigned long long d;
    asm("fma.rn.f32x2 %0, %1, %2, %3;" : "=l"(d) : "l"(a), "l"(b), "l"(c));
    return d;
}

// ---------------- setup: depths + homographies ----------------
__global__ void setup_kernel(const float* __restrict__ K, const float* __restrict__ poses) {
    for (int i = 0; i < ND; i++) {
        float inv = 2.0f + (float)i * (0.2f - 2.0f) / 127.0f;
        g_depths[i] = 1.0f / inv;
    }
    float fx = K[0] / 8.0f, cx = K[2] / 8.0f, fy = K[4] / 8.0f, cy = K[5] / 8.0f;
    float Kf[9] = {fx, 0, cx, 0, fy, cy, 0, 0, 1};
    float Ki[9] = {1.0f/fx, 0, -cx/fx, 0, 1.0f/fy, -cy/fy, 0, 0, 1};
    float R0T[9], ti[3];
    for (int r = 0; r < 3; r++)
        for (int c = 0; c < 3; c++) R0T[r*3+c] = poses[c*4+r];
    for (int r = 0; r < 3; r++) {
        float s = 0;
        for (int c = 0; c < 3; c++) s += R0T[r*3+c] * poses[c*4+3];
        ti[r] = -s;
    }
    for (int v = 1; v < NV; v++) {
        const float* P = poses + v*16;
        float Rt[9], tt[3], A[9];
        for (int r = 0; r < 3; r++)
            for (int c = 0; c < 3; c++) {
                float s = 0;
                for (int k = 0; k < 3; k++) s += P[r*4+k] * R0T[k*3+c];
                Rt[r*3+c] = s;
            }
        for (int r = 0; r < 3; r++) {
            float s = 0;
            for (int k = 0; k < 3; k++) s += P[r*4+k] * ti[k];
            tt[r] = s + P[r*4+3];
        }
        for (int r = 0; r < 3; r++)
            for (int c = 0; c < 3; c++) {
                float s = 0;
                for (int k = 0; k < 3; k++) s += Kf[r*3+k] * Rt[k*3+c];
                A[r*3+c] = s;
            }
        for (int r = 0; r < 3; r++)
            for (int c = 0; c < 3; c++) {
                float s = 0;
                for (int k = 0; k < 3; k++) s += A[r*3+k] * Ki[k*3+c];
                g_Hm[(v-1)*9 + r*3 + c] = s;
            }
        for (int r = 0; r < 3; r++) {
            float s = 0;
            for (int k = 0; k < 3; k++) s += Kf[r*3+k] * tt[k];
            g_bb[(v-1)*3 + r] = s;
        }
    }
}

// ---------------- encoder (round-15 tiling: the 359us config) ----------------
// enc1: 3 -> 8 ch, stride 2; thread = (im, y, 4 x-outputs)
__global__ __launch_bounds__(256) void enc1_kernel(const float* __restrict__ img,
                                                   const float* __restrict__ w,
                                                   const float* __restrict__ b) {
    __shared__ float sw[8*3*9];
    __shared__ float sb[8];
    for (int i = threadIdx.x; i < 8*3*9; i += blockDim.x) sw[i] = w[i];
    if (threadIdx.x < 8) sb[threadIdx.x] = b[threadIdx.x];
    __syncthreads();
    int idx = blockIdx.x * blockDim.x + threadIdx.x;
    const int XG = W1/4;  // 80
    if (idx >= NV*H1*XG) return;
    int xg = idx % XG, y = (idx / XG) % H1, im = idx / (XG*H1);
    int xb = xg * 4;
    float acc[8][4];
#pragma unroll
    for (int o = 0; o < 8; o++) {
        float bv = sb[o];
#pragma unroll
        for (int xi = 0; xi < 4; xi++) acc[o][xi] = bv;
    }
    const float* ib = img + im*3*HWI;
    for (int ic = 0; ic < 3; ic++) {
#pragma unroll
        for (int ky = 0; ky < 3; ky++) {
            int iy = 2*y + ky; if (iy >= HIMG) continue;
            const float* row = ib + (ic*HIMG + iy)*WIMG + 2*xb;
            float v[9];
            float4 q0 = *(const float4*)row;
            float4 q1 = *(const float4*)(row + 4);
            v[0]=q0.x; v[1]=q0.y; v[2]=q0.z; v[3]=q0.w;
            v[4]=q1.x; v[5]=q1.y; v[6]=q1.z; v[7]=q1.w;
            v[8] = (2*xb + 8 < WIMG) ? row[8] : 0.0f;
#pragma unroll
            for (int kx = 0; kx < 3; kx++) {
#pragma unroll
                for (int o = 0; o < 8; o++) {
                    float wv = sw[((o*3+ic)*3+ky)*3+kx];
#pragma unroll
                    for (int xi = 0; xi < 4; xi++)
                        acc[o][xi] += v[2*xi + kx] * wv;
                }
            }
        }
    }
#pragma unroll
    for (int o = 0; o < 8; o++)
#pragma unroll
        for (int xi = 0; xi < 4; xi++)
            g_e1[((im*8+o)*H1 + y)*W1 + xb + xi] = fmaxf(acc[o][xi], 0.0f);
}

// enc2: 8 -> 16 ch, stride 2; thread = (im, y, 2 x-outputs)
__global__ __launch_bounds__(256) void enc2_kernel(const float* __restrict__ w,
                                                   const float* __restrict__ b) {
    __shared__ float sw[16*8*9];
    __shared__ float sb[16];
    for (int i = threadIdx.x; i < 16*8*9; i += blockDim.x) sw[i] = w[i];
    if (threadIdx.x < 16) sb[threadIdx.x] = b[threadIdx.x];
    __syncthreads();
    int idx = blockIdx.x * blockDim.x + threadIdx.x;
    const int XG = W2/2;  // 80
    if (idx >= NV*H2*XG) return;
    int xg = idx % XG, y = (idx / XG) % H2, im = idx / (XG*H2);
    int xb = xg * 2;
    float acc[16][2];
#pragma unroll
    for (int o = 0; o < 16; o++) {
        float bv = sb[o];
        acc[o][0] = bv; acc[o][1] = bv;
    }
    const float* ib = g_e1 + im*8*H1*W1;
    for (int ic = 0; ic < 8; ic++) {
#pragma unroll
        for (int ky = 0; ky < 3; ky++) {
            int iy = 2*y + ky; if (iy >= H1) continue;
            const float* row = ib + (ic*H1 + iy)*W1 + 2*xb;
            float v[5];
            float4 q0 = *(const float4*)row;
            v[0]=q0.x; v[1]=q0.y; v[2]=q0.z; v[3]=q0.w;
            v[4] = (2*xb + 4 < W1) ? row[4] : 0.0f;
#pragma unroll
            for (int kx = 0; kx < 3; kx++) {
#pragma unroll
                for (int o = 0; o < 16; o++) {
                    float wv = sw[((o*8+ic)*3+ky)*3+kx];
                    acc[o][0] += v[kx] * wv;
                    acc[o][1] += v[2 + kx] * wv;
                }
            }
        }
    }
#pragma unroll
    for (int o = 0; o < 16; o++) {
        g_e2[((im*16+o)*H2 + y)*W2 + xb]     = fmaxf(acc[o][0], 0.0f);
        g_e2[((im*16+o)*H2 + y)*W2 + xb + 1] = fmaxf(acc[o][1], 0.0f);
    }
}

// enc3: 16 -> 32 ch, stride 2; thread = (im, y, 2 x-outputs), oc group of 8 via grid.y
__global__ __launch_bounds__(128) void enc3_kernel(const float* __restrict__ w,
                                                   const float* __restrict__ b) {
    __shared__ float sw[8*16*9];
    __shared__ float sb[8];
    int ocg = blockIdx.y;  // 0..3
    for (int i = threadIdx.x; i < 8*16*9; i += blockDim.x) {
        int o = i / 144, rest = i % 144;
        sw[i] = w[(ocg*8 + o)*144 + rest];
    }
    if (threadIdx.x < 8) sb[threadIdx.x] = b[ocg*8 + threadIdx.x];
    __syncthreads();
    int idx = blockIdx.x * blockDim.x + threadIdx.x;
    const int XG = WFE/2;  // 40
    if (idx >= NV*HFE*XG) return;
    int xg = idx % XG, y = (idx / XG) % HFE, im = idx / (XG*HFE);
    int xb = xg * 2;
    float acc[8][2];
#pragma unroll
    for (int o = 0; o < 8; o++) {
        float bv = sb[o];
        acc[o][0] = bv; acc[o][1] = bv;
    }
    const float* ib = g_e2 + im*16*H2*W2;
    for (int ic = 0; ic < 16; ic++) {
#pragma unroll
        for (int ky = 0; ky < 3; ky++) {
            int iy = 2*y + ky; if (iy >= H2) continue;
            const float* row = ib + (ic*H2 + iy)*W2 + 2*xb;
            float v[5];
            float4 q0 = *(const float4*)row;
            v[0]=q0.x; v[1]=q0.y; v[2]=q0.z; v[3]=q0.w;
            v[4] = (2*xb + 4 < W2) ? row[4] : 0.0f;
#pragma unroll
            for (int kx = 0; kx < 3; kx++) {
#pragma unroll
                for (int o = 0; o < 8; o++) {
                    float wv = sw[(o*16+ic)*9 + ky*3 + kx];
                    acc[o][0] += v[kx] * wv;
                    acc[o][1] += v[2 + kx] * wv;
                }
            }
        }
    }
#pragma unroll
    for (int xi = 0; xi < 2; xi++) {
        int pix = y*WFE + xb + xi;
        __half2 l01 = __floats2half2_rn(acc[0][xi], acc[1][xi]);
        __half2 l23 = __floats2half2_rn(acc[2][xi], acc[3][xi]);
        __half2 h01 = __floats2half2_rn(acc[4][xi], acc[5][xi]);
        __half2 h23 = __floats2half2_rn(acc[6][xi], acc[7][xi]);
        uint2 ulo = make_uint2(*reinterpret_cast<unsigned*>(&l01),
                               *reinterpret_cast<unsigned*>(&l23));
        uint2 uhi = make_uint2(*reinterpret_cast<unsigned*>(&h01),
                               *reinterpret_cast<unsigned*>(&h23));
        g_featsh2[(im*8 + ocg*2 + 0)*HWF + pix] = ulo;
        g_featsh2[(im*8 + ocg*2 + 1)*HWF + pix] = uhi;
    }
}

// ---------------- cost volume: fp16 feats in, fp16 padded pixel-major out ----------------
__device__ __forceinline__ void unpack_h4(uint2 u, float& a, float& b, float& c, float& d) {
    __half2 h0 = *reinterpret_cast<__half2*>(&u.x);
    __half2 h1 = *reinterpret_cast<__half2*>(&u.y);
    float2 f0 = __half22float2(h0), f1 = __half22float2(h1);
    a = f0.x; b = f0.y; c = f1.x; d = f1.y;
}

__global__ __launch_bounds__(256) void cost_kernel() {
    int idx = blockIdx.x * blockDim.x + threadIdx.x;
    if (idx >= NPADPIX) return;
    int xp = idx % XP, yp = (idx / XP) % YP, dp = idx / (XP*YP);
    uint2* cp = (uint2*)g_costp4;
    bool interior = (xp >= 1) && (xp <= WFE) && (yp >= 1) && (yp <= HFE)
                 && (dp >= 1) && (dp <= ND);
    if (!interior) {
#pragma unroll
        for (int j = 0; j < 8; j++) cp[idx*8 + j] = make_uint2(0u, 0u);
        return;
    }
    int x = xp - 1, y = yp - 1, d = dp - 1;
    float depth = g_depths[d];
    float xf = (float)x, yf = (float)y;
    float wgt[4][4];
    int   off[4][4];
#pragma unroll
    for (int v = 0; v < 4; v++) {
        const float* Hm = g_Hm + v*9;
        const float* bb = g_bb + v*3;
        float u  = depth*(Hm[0]*xf + Hm[1]*yf + Hm[2]) + bb[0];
        float vv = depth*(Hm[3]*xf + Hm[4]*yf + Hm[5]) + bb[1];
        float z  = depth*(Hm[6]*xf + Hm[7]*yf + Hm[8]) + bb[2];
        float valid = z > 0.001f ? 1.0f : 0.0f;
        float zc = fmaxf(z, 0.001f);
        float px = u / zc, py = vv / zc;
        float fx0 = floorf(px), fy0 = floorf(py);
        float wx = px - fx0, wy = py - fy0;
        int x0 = (int)fx0, y0 = (int)fy0;
        float w00 = (1.0f-wx)*(1.0f-wy)*valid;
        float w01 = wx*(1.0f-wy)*valid;
        float w10 = (1.0f-wx)*wy*valid;
        float w11 = wx*wy*valid;
        bool ix0 = (x0 >= 0) && (x0 < WFE);
        bool ix1 = (x0+1 >= 0) && (x0+1 < WFE);
        bool iy0 = (y0 >= 0) && (y0 < HFE);
        bool iy1 = (y0+1 >= 0) && (y0+1 < HFE);
        if (!(ix0 && iy0)) w00 = 0.0f;
        if (!(ix1 && iy0)) w01 = 0.0f;
        if (!(ix0 && iy1)) w10 = 0.0f;
        if (!(ix1 && iy1)) w11 = 0.0f;
        int cx0 = min(max(x0, 0), WFE-1), cx1 = min(max(x0+1, 0), WFE-1);
        int cy0 = min(max(y0, 0), HFE-1), cy1 = min(max(y0+1, 0), HFE-1);
        wgt[v][0] = w00; wgt[v][1] = w01; wgt[v][2] = w10; wgt[v][3] = w11;
        off[v][0] = cy0*WFE + cx0; off[v][1] = cy0*WFE + cx1;
        off[v][2] = cy1*WFE + cx0; off[v][3] = cy1*WFE + cx1;
    }
    int pix = y*WFE + x;
#pragma unroll 2
    for (int c4 = 0; c4 < 8; c4++) {
        float s0, s1, s2, s3;
        unpack_h4(g_featsh2[c4*HWF + pix], s0, s1, s2, s3);
        float q0 = s0*s0, q1 = s1*s1, q2 = s2*s2, q3 = s3*s3;
#pragma unroll
        for (int v = 0; v < 4; v++) {
            const uint2* pl = g_featsh2 + ((v+1)*8 + c4)*HWF;
            float ax, ay, az, aw, bx, by, bz, bw;
            float cx, cy, cz, cw, ex, ey, ez, ew;
            unpack_h4(pl[off[v][0]], ax, ay, az, aw);
            unpack_h4(pl[off[v][1]], bx, by, bz, bw);
            unpack_h4(pl[off[v][2]], cx, cy, cz, cw);
            unpack_h4(pl[off[v][3]], ex, ey, ez, ew);
            float w00 = wgt[v][0], w01 = wgt[v][1], w10 = wgt[v][2], w11 = wgt[v][3];
            float v0 = w00*ax + w01*bx + w10*cx + w11*ex;
            float v1 = w00*ay + w01*by + w10*cy + w11*ey;
            float v2 = w00*az + w01*bz + w10*cz + w11*ez;
            float v3 = w00*aw + w01*bw + w10*cw + w11*ew;
            s0 += v0; q0 += v0*v0;
            s1 += v1; q1 += v1*v1;
            s2 += v2; q2 += v2*v2;
            s3 += v3; q3 += v3*v3;
        }
        float m0 = s0*0.2f, m1 = s1*0.2f, m2 = s2*0.2f, m3 = s3*0.2f;
        __half2 ha = __floats2half2_rn(q0*0.2f - m0*m0, q1*0.2f - m1*m1);
        __half2 hb = __floats2half2_rn(q2*0.2f - m2*m2, q3*0.2f - m3*m3);
        unsigned ua = *reinterpret_cast<unsigned*>(&ha);
        unsigned ub = *reinterpret_cast<unsigned*>(&hb);
        cp[idx*8 + c4] = make_uint2(ua, ub);
    }
}

// ---------------- reg1: fp16 tensor-core implicit GEMM (27-tap accumulation) ----------------
#define R1M_ICS 40
#define R1M_A_BYTES (12*82*R1M_ICS*2)
#define R1M_B_BYTES (54*8*16*2)
#define R1M_SMEM (R1M_A_BYTES + R1M_B_BYTES)

__global__ __launch_bounds__(320) void reg1_mma_kernel(const float* __restrict__ w,
                                                       const float* __restrict__ b) {
    extern __shared__ char sm[];
    __half* sB = (__half*)(sm + R1M_A_BYTES);
    int tid = threadIdx.x;
    int by = blockIdx.x & 31, d0 = blockIdx.x >> 5;
    int y0 = by * 2;

    uint4* sA4 = (uint4*)sm;
    for (int e = tid; e < 12*82*4; e += 320) {
        int u = e & 3;
        int px = (e >> 2) % 82;
        int r = e / 328;
        int kdl = r >> 2, kyl = r & 3;
        int pixpad = (((d0 + kdl)*YP) + (y0 + kyl))*XP + px;
        sA4[(r*82 + px)*5 + u] = g_costp4[pixpad*4 + u];
    }
    for (int e = tid; e < 54*8*16; e += 320) {
        int k = e & 15, oc = (e >> 4) & 7, tc = e >> 7;
        int tap = tc >> 1, ch = tc & 1;
        sB[e] = __float2half(w[oc*864 + (ch*16 + k)*27 + tap]);
    }
    __syncthreads();

    int warp = tid >> 5, lane = tid & 31;
    int ybase = warp / 5, xt = warp % 5;
    int ocp = lane & 3;
    float c0 = b[2*ocp], c1 = b[2*ocp + 1];
    float c2 = c0, c3 = c1;
    unsigned sA_base = (unsigned)__cvta_generic_to_shared(sm);
    unsigned sB_base = (unsigned)__cvta_generic_to_shared(sB);
    int r_l = (lane < 16) ? lane : lane - 16;
    unsigned c_l = (lane < 16) ? 0u : 16u;
    unsigned boff = (unsigned)((lane >> 2)*32 + ocp*4);

#pragma unroll
    for (int kd = 0; kd < 3; kd++) {
#pragma unroll
        for (int ky = 0; ky < 3; ky++) {
#pragma unroll
            for (int kx = 0; kx < 3; kx++) {
                int tap = (kd*3 + ky)*3 + kx;
                int pixrow = (kd*4 + ybase + ky)*82 + xt*16 + kx;
                unsigned abase = sA_base + (unsigned)((pixrow + r_l)*80) + c_l;
#pragma unroll
                for (int ch = 0; ch < 2; ch++) {
                    unsigned aaddr = abase + (unsigned)(ch*32);
                    unsigned a0, a1, a2, a3;
                    asm volatile(
                        "ldmatrix.sync.aligned.m8n8.x4.shared.b16 {%0,%1,%2,%3}, [%4];"
                        : "=r"(a0), "=r"(a1), "=r"(a2), "=r"(a3) : "r"(aaddr));
                    unsigned baddr = sB_base + (unsigned)((tap*2 + ch)*256) + boff;
                    unsigned b0, b1;
                    asm volatile("ld.shared.b32 %0, [%1];" : "=r"(b0) : "r"(baddr));
                    asm volatile("ld.shared.b32 %0, [%1];" : "=r"(b1) : "r"(baddr + 16));
                    asm volatile(
                        "mma.sync.aligned.m16n8k16.row.col.f32.f16.f16.f32 "
                        "{%0,%1,%2,%3}, {%4,%5,%6,%7}, {%8,%9}, {%0,%1,%2,%3};"
                        : "+f"(c0), "+f"(c1), "+f"(c2), "+f"(c3)
                        : "r"(a0), "r"(a1), "r"(a2), "r"(a3), "r"(b0), "r"(b1));
                }
            }
        }
    }

    int y = y0 + ybase;
    __half2* grh = (__half2*)g_reg1h4;
    int row0 = xt*16 + (lane >> 2);
    int base0 = ((d0*HFE + y)*WFE + row0)*4 + ocp;
    int base1 = ((d0*HFE + y)*WFE + row0 + 8)*4 + ocp;
    grh[base0] = __floats2half2_rn(fmaxf(c0, 0.0f), fmaxf(c1, 0.0f));
    grh[base1] = __floats2half2_rn(fmaxf(c2, 0.0f), fmaxf(c3, 0.0f));
}

// reg2: 8 -> 1 ch, 3x3x3 SAME; thread = (d, y, 2 x); taps read as 1x uint4 (8 fp16)
__global__ __launch_bounds__(256) void reg2_kernel(const float* __restrict__ w,
                                                   const float* __restrict__ b) {
    __shared__ float sw[27*8];
    __shared__ float sb0;
    for (int i = threadIdx.x; i < 27*8; i += blockDim.x) {
        int k = i >> 3, oc = i & 7;
        sw[i] = w[oc*27 + k];
    }
    if (threadIdx.x == 0) sb0 = b[0];
    __syncthreads();
    int idx = blockIdx.x * blockDim.x + threadIdx.x;
    const int XG = WFE/2;
    if (idx >= ND*HFE*XG) return;
    int xg = idx % XG, y = (idx / XG) % HFE, d = idx / (XG*HFE);
    int xb = xg * 2;
    float acc0 = sb0, acc1 = sb0;
#pragma unroll
    for (int kd = 0; kd < 3; kd++) {
        int dd = d + kd - 1; if (dd < 0 || dd >= ND) continue;
#pragma unroll
        for (int ky = 0; ky < 3; ky++) {
            int yy = y + ky - 1; if (yy < 0 || yy >= HFE) continue;
            int rowbase = (dd*HFE + yy)*WFE;
            uint4 v[4];
#pragma unroll
            for (int j = 0; j < 4; j++) {
                int xx = xb - 1 + j;
                v[j] = (xx >= 0 && xx < WFE) ? g_reg1h4[rowbase + xx]
                                             : make_uint4(0u, 0u, 0u, 0u);
            }
#pragma unroll
            for (int kx = 0; kx < 3; kx++) {
                const float* wk = sw + (kd*9 + ky*3 + kx)*8;
                const __half2* h0 = (const __half2*)&v[kx];
                const __half2* h1 = (const __half2*)&v[kx+1];
#pragma unroll
                for (int q = 0; q < 4; q++) {
                    float2 f0 = __half22float2(h0[q]);
                    float2 f1 = __half22float2(h1[q]);
                    acc0 += f0.x*wk[2*q] + f0.y*wk[2*q+1];
                    acc1 += f1.x*wk[2*q] + f1.y*wk[2*q+1];
                }
            }
        }
    }
    g_cost2[(d*HFE + y)*WFE + xb]     = acc0;
    g_cost2[(d*HFE + y)*WFE + xb + 1] = acc1;
}

// ---------------- streaming softmax + sum4 confidence + depth regression ----------------
__global__ __launch_bounds__(256) void softmax_kernel() {
    int pix = blockIdx.x * blockDim.x + threadIdx.x;
    if (pix >= HWF) return;
    const float* col = g_cost2 + pix;
    float m = -1e30f;
#pragma unroll 8
    for (int d = 0; d < ND; d++)
        m = fmaxf(m, col[d*HWF]);
    float s = 0.0f, sd = 0.0f, mw = 0.0f;
    float e1 = 0.0f, e2 = 0.0f, e3 = 0.0f;
#pragma unroll 4
    for (int d = 0; d < ND; d++) {
        float e0 = expf(col[d*HWF] - m);
        s += e0;
        sd += e0 * g_depths[d];
        float win = e0 + e1 + e2 + e3;
        if (d >= 3) mw = fmaxf(mw, win);
        e3 = e2; e2 = e1; e1 = e0;
    }
    g_conf[pix] = mw / s;
    g_regd[pix] = sd / s;
}

// ---------------- x8 bilinear upsample ----------------
__global__ __launch_bounds__(256) void upsample_kernel(float* __restrict__ out_conf) {
    int idx = blockIdx.x * blockDim.x + threadIdx.x;
    if (idx >= HWI) return;
    int ox = idx % WIMG, oy = idx / WIMG;
    float fy = (oy + 0.5f) * ((float)HFE / HIMG) - 0.5f;
    float fx = (ox + 0.5f) * ((float)WFE / WIMG) - 0.5f;
    float y0f = floorf(fy), x0f = floorf(fx);
    float wy = fy - y0f, wx = fx - x0f;
    int y0 = (int)y0f, x0 = (int)x0f;
    int y0c = min(max(y0, 0), HFE-1), y1c = min(max(y0+1, 0), HFE-1);
    int x0c = min(max(x0, 0), WFE-1), x1c = min(max(x0+1, 0), WFE-1);
    float w00 = (1.0f-wx)*(1.0f-wy), w01 = wx*(1.0f-wy);
    float w10 = (1.0f-wx)*wy, w11 = wx*wy;
    float cv = w00*g_conf[y0c*WFE+x0c] + w01*g_conf[y0c*WFE+x1c]
             + w10*g_conf[y1c*WFE+x0c] + w11*g_conf[y1c*WFE+x1c];
    float rv = w00*g_regd[y0c*WFE+x0c] + w01*g_regd[y0c*WFE+x1c]
             + w10*g_regd[y1c*WFE+x0c] + w11*g_regd[y1c*WFE+x1c];
    out_conf[idx] = cv;
    g_regup[idx] = rv;
}

// ---------------- refinement ----------------
// refine1: 4 -> 32 ch, f32x2 oc-pair packed; stores fp16 pixel-major
__global__ __launch_bounds__(256) void refine1_kernel(const float* __restrict__ img,
                                                      const float* __restrict__ w,
                                                      const float* __restrict__ b) {
    __shared__ unsigned long long sw2[8*4*9];   // [pair][ic][k] (w[2p], w[2p+1])
    __shared__ unsigned long long sb2[8];
    int ocg = blockIdx.y;
    for (int i = threadIdx.x; i < 8*4*9; i += blockDim.x) {
        int pair = i / 36, rest = i % 36;
        float lo = w[((ocg*16 + 2*pair)*4)*9 + rest];
        float hi = w[((ocg*16 + 2*pair + 1)*4)*9 + rest];
        sw2[i] = pk2(lo, hi);
    }
    if (threadIdx.x < 8)
        sb2[threadIdx.x] = pk2(b[ocg*16 + 2*threadIdx.x], b[ocg*16 + 2*threadIdx.x + 1]);
    __syncthreads();
    int id = blockIdx.x * blockDim.x + threadIdx.x;
    const int XG = WIMG/4;
    if (id >= HIMG*XG) return;
    int xg = id % XG, y = id / XG;
    int xb = xg * 4;
    unsigned long long acc2[8][4];
#pragma unroll
    for (int p = 0; p < 8; p++) {
        unsigned long long bv = sb2[p];
#pragma unroll
        for (int xi = 0; xi < 4; xi++) acc2[p][xi] = bv;
    }
    for (int ic = 0; ic < 4; ic++) {
        const float* src = (ic < 3) ? (img + ic*HWI) : g_regup;
#pragma unroll
        for (int ky = 0; ky < 3; ky++) {
            int yy = y + ky - 1; if (yy < 0 || yy >= HIMG) continue;
            const float* row = src + yy*WIMG;
            unsigned long long v2[6];
#pragma unroll
            for (int j = 0; j < 6; j++) {
                int xx = xb - 1 + j;
                float v = (xx >= 0 && xx < WIMG) ? row[xx] : 0.0f;
                v2[j] = pk2(v, v);
            }
#pragma unroll
            for (int kx = 0; kx < 3; kx++) {
#pragma unroll
                for (int p = 0; p < 8; p++) {
                    unsigned long long wv2 = sw2[(p*4 + ic)*9 + ky*3 + kx];
#pragma unroll
                    for (int xi = 0; xi < 4; xi++)
                        acc2[p][xi] = fma2(v2[kx + xi], wv2, acc2[p][xi]);
                }
            }
        }
    }
#pragma unroll
    for (int xi = 0; xi < 4; xi++) {
        int pix = y*WIMG + xb + xi;
#pragma unroll
        for (int q2 = 0; q2 < 2; q2++) {
            __half2 hs[4];
#pragma unroll
            for (int p = 0; p < 4; p++) {
                float lo, hi;
                upk2(lo, hi, acc2[q2*4 + p][xi]);
                hs[p] = __floats2half2_rn(fmaxf(lo, 0.0f), fmaxf(hi, 0.0f));
            }
            uint4 u;
            u.x = *reinterpret_cast<unsigned*>(&hs[0]);
            u.y = *reinterpret_cast<unsigned*>(&hs[1]);
            u.z = *reinterpret_cast<unsigned*>(&hs[2]);
            u.w = *reinterpret_cast<unsigned*>(&hs[3]);
            g_hiddenh4[pix*4 + ocg*2 + q2] = u;
        }
    }
}

// refine2: 32 -> 1 ch; taps read as 4x uint4 (32 fp16)
__global__ __launch_bounds__(256) void refine2_kernel(const float* __restrict__ w,
                                                      const float* __restrict__ b,
                                                      float* __restrict__ out_ref) {
    __shared__ float sw[32*9];
    __shared__ float sb0;
    for (int i = threadIdx.x; i < 32*9; i += blockDim.x) sw[i] = w[i];
    if (threadIdx.x == 0) sb0 = b[0];
    __syncthreads();
    int idx = blockIdx.x * blockDim.x + threadIdx.x;
    if (idx >= HWI) return;
    int x = idx % WIMG, y = idx / WIMG;
    float acc = sb0;
#pragma unroll
    for (int ky = 0; ky < 3; ky++) {
        int yy = y + ky - 1; if (yy < 0 || yy >= HIMG) continue;
#pragma unroll
        for (int kx = 0; kx < 3; kx++) {
            int xx = x + kx - 1; if (xx < 0 || xx >= WIMG) continue;
            int pix = yy*WIMG + xx;
            int tap = ky*3 + kx;
#pragma unroll
            for (int q = 0; q < 4; q++) {
                uint4 h4 = g_hiddenh4[pix*4 + q];
                const __half2* hp = (const __half2*)&h4;
#pragma unroll
                for (int p = 0; p < 4; p++) {
                    float2 f = __half22float2(hp[p]);
                    acc += f.x * sw[(q*8 + 2*p)*9 + tap];
                    acc += f.y * sw[(q*8 + 2*p + 1)*9 + tap];
                }
            }
        }
    }
    out_ref[idx] = g_regup[idx] + acc;
}

// ---------------- launch ----------------
extern "C" void kernel_launch(void* const* d_in, const int* in_sizes, int n_in,
                              void* d_out, int out_size) {
    const float* images = (const float*)d_in[0];
    const float* K      = (const float*)d_in[1];
    const float* poses  = (const float*)d_in[2];
    const float* enc_w1 = (const float*)d_in[3];
    const float* enc_b1 = (const float*)d_in[4];
    const float* enc_w2 = (const float*)d_in[5];
    const float* enc_b2 = (const float*)d_in[6];
    const float* enc_w3 = (const float*)d_in[7];
    const float* enc_b3 = (const float*)d_in[8];
    const float* reg_w1 = (const float*)d_in[9];
    const float* reg_b1 = (const float*)d_in[10];
    const float* reg_w2 = (const float*)d_in[11];
    const float* reg_b2 = (const float*)d_in[12];
    const float* ref_w1 = (const float*)d_in[13];
    const float* ref_b1 = (const float*)d_in[14];
    const float* ref_w2 = (const float*)d_in[15];
    const float* ref_b2 = (const float*)d_in[16];
    float* out = (float*)d_out;

    cudaFuncSetAttribute(reg1_mma_kernel, cudaFuncAttributeMaxDynamicSharedMemorySize,
                         R1M_SMEM);

    setup_kernel<<<1, 1>>>(K, poses);
    enc1_kernel<<<(NV*H1*(W1/4) + 255)/256, 256>>>(images, enc_w1, enc_b1);
    enc2_kernel<<<(NV*H2*(W2/2) + 255)/256, 256>>>(enc_w2, enc_b2);
    dim3 g3((NV*HFE*(WFE/2) + 127)/128, 4);
    enc3_kernel<<<g3, 128>>>(enc_w3, enc_b3);
    cost_kernel<<<(NPADPIX + 255)/256, 256>>>();
    reg1_mma_kernel<<<ND*32, 320, R1M_SMEM>>>(reg_w1, reg_b1);
    reg2_kernel<<<(ND*HFE*(WFE/2) + 255)/256, 256>>>(reg_w2, reg_b2);
    softmax_kernel<<<(HWF + 255)/256, 256>>>();
    upsample_kernel<<<(HWI + 255)/256, 256>>>(out);
    dim3 g1((HIMG*(WIMG/4) + 255)/256, 2);
    refine1_kernel<<<g1, 256>>>(images, ref_w1, ref_b1);
    refine2_kernel<<<(HWI + 255)/256, 256>>>(ref_w2, ref_b2, out + HWI);
}